// round 6
// baseline (speedup 1.0000x reference)
#include <cuda_runtime.h>
#include <cuda_fp16.h>
#include <math.h>

#define BB 4
#define NN 8192
#define FF 64
#define H1 64
#define H2 32
#define K2P 36            // padded half2 pairs per W1 row (67 inputs + bias + pad)
#define CPB 32            // CTAs (chunks) per batch = 8192/256

__device__ __forceinline__ __half2 u2h2(unsigned int u) {
    return *reinterpret_cast<__half2*>(&u);
}

// ---- scratch (static, no allocation) ----
__device__ float g_csum[BB * CPB];
__device__ float g_csq[BB * CPB];
__device__ int   g_ccnt[BB * CPB];     // selected (>0.7) per chunk
__device__ int   g_cmask[BB * CPB];    // mask count per chunk
__device__ int   g_sel[BB][NN];        // per-chunk compacted selected indices

// ============================================================
// Kernel 1: per-point MLP 67 -> 64 -> 32 -> 1 (+mask) in fp16x2,
// plus fused per-chunk stats + selected-index compaction epilogue.
// ============================================================
__global__ __launch_bounds__(256) void mlp_kernel(
    const float* __restrict__ points, const float* __restrict__ features,
    const int* __restrict__ mask,
    const float* __restrict__ W1, const float* __restrict__ b1,
    const float* __restrict__ W2, const float* __restrict__ b2,
    const float* __restrict__ W3, const float* __restrict__ b3,
    float* __restrict__ scores, float* __restrict__ out_feats)
{
    __shared__ __align__(16) __half2 sW1h[H1][K2P];   // 9216B
    __shared__ __align__(16) __half2 sW2h[H2][H1/2];  // 4096B
    __shared__ float sb2[H2];
    __shared__ float sW3[H2];
    __shared__ float sb3;
    __shared__ float rsum[8], rsq[8];
    __shared__ int rcnt[8], rmask[8], roff[8];

    int tid = threadIdx.x;

    // ---- pack W1 (+bias1) into half2 [64][36] ----
    for (int idx = tid; idx < H1 * K2P; idx += 256) {
        int j = idx / K2P, k2 = idx % K2P;
        float a = 0.f, bv = 0.f;
        if (k2 <= 33) {
            int k = 2 * k2;
            a  = (k     < 67) ? W1[j * 67 + k]     : 0.f;
            bv = (k + 1 < 67) ? W1[j * 67 + k + 1] : 0.f;
        } else if (k2 == 34) {
            a = b1[j];                 // bias slot, x2[34] = (1, 0)
        }
        sW1h[j][k2] = __floats2half2_rn(a, bv);
    }
    // ---- pack W2 into half2 [32][32] ----
    for (int idx = tid; idx < H2 * (H1 / 2); idx += 256) {
        int i = idx / (H1 / 2), j2 = idx % (H1 / 2);
        sW2h[i][j2] = __floats2half2_rn(W2[i * H1 + 2 * j2], W2[i * H1 + 2 * j2 + 1]);
    }
    if (tid < H2) { sb2[tid] = b2[tid]; sW3[tid] = W3[tid]; }
    if (tid == 0) sb3 = b3[0];
    __syncthreads();

    int p = blockIdx.x * 256 + tid;   // global point id over B*N (grid exact)

    // ---- load input, stream features passthrough, pack x to half2 ----
    __half2 x2[K2P];
    const float4* f4 = (const float4*)(features + (size_t)p * FF);
    float4* o4 = (float4*)(out_feats + (size_t)p * FF);
#pragma unroll
    for (int i = 0; i < FF / 4; i++) {
        float4 v = f4[i];
        o4[i] = v;
        x2[2 * i]     = __floats2half2_rn(v.x, v.y);
        x2[2 * i + 1] = __floats2half2_rn(v.z, v.w);
    }
    const float* pp = points + (size_t)p * 3;
    x2[32] = __floats2half2_rn(pp[0], pp[1]);
    x2[33] = __floats2half2_rn(pp[2], 0.f);
    x2[34] = __floats2half2_rn(1.f, 0.f);     // bias slot
    x2[35] = __floats2half2_rn(0.f, 0.f);

    // ---- layer-2 accumulators initialized with bias (lane 0) ----
    __half2 h2acc[H2];
#pragma unroll
    for (int i = 0; i < H2; i++) h2acc[i] = __floats2half2_rn(sb2[i], 0.f);

    // ---- layer 1 in groups of 8 outputs, streamed into layer 2 ----
    for (int jg = 0; jg < H1 / 8; jg++) {
        float h[8];
#pragma unroll
        for (int jj = 0; jj < 8; jj++) {
            const uint4* row = reinterpret_cast<const uint4*>(sW1h[jg * 8 + jj]);
            __half2 aa = __floats2half2_rn(0.f, 0.f);
            __half2 ab = __floats2half2_rn(0.f, 0.f);
#pragma unroll
            for (int q = 0; q < 9; q++) {
                uint4 w = row[q];
                aa = __hfma2(u2h2(w.x), x2[4 * q],     aa);
                ab = __hfma2(u2h2(w.y), x2[4 * q + 1], ab);
                aa = __hfma2(u2h2(w.z), x2[4 * q + 2], aa);
                ab = __hfma2(u2h2(w.w), x2[4 * q + 3], ab);
            }
            float2 f = __half22float2(__hadd2(aa, ab));
            h[jj] = fmaxf(f.x + f.y, 0.f);
        }
        __half2 hp[4];
#pragma unroll
        for (int t = 0; t < 4; t++) hp[t] = __floats2half2_rn(h[2 * t], h[2 * t + 1]);

#pragma unroll
        for (int i = 0; i < H2; i++) {
            uint4 w = reinterpret_cast<const uint4*>(sW2h[i])[jg];
            h2acc[i] = __hfma2(u2h2(w.x), hp[0], h2acc[i]);
            h2acc[i] = __hfma2(u2h2(w.y), hp[1], h2acc[i]);
            h2acc[i] = __hfma2(u2h2(w.z), hp[2], h2acc[i]);
            h2acc[i] = __hfma2(u2h2(w.w), hp[3], h2acc[i]);
        }
    }

    // ---- layer 3 (fp32): relu(h2) dot W3, 4 chains ----
    float z0 = 0.f, z1 = 0.f, z2 = 0.f, z3 = 0.f;
#pragma unroll
    for (int i = 0; i < H2; i += 4) {
        float2 f0 = __half22float2(h2acc[i]);
        float2 f1 = __half22float2(h2acc[i + 1]);
        float2 f2 = __half22float2(h2acc[i + 2]);
        float2 f3 = __half22float2(h2acc[i + 3]);
        z0 += sW3[i]     * fmaxf(f0.x + f0.y, 0.f);
        z1 += sW3[i + 1] * fmaxf(f1.x + f1.y, 0.f);
        z2 += sW3[i + 2] * fmaxf(f2.x + f2.y, 0.f);
        z3 += sW3[i + 3] * fmaxf(f3.x + f3.y, 0.f);
    }
    float z = sb3 + (z0 + z1) + (z2 + z3);
    float sv = 1.0f / (1.0f + expf(-z));

    int m = mask[p];
    float score = (m != 0) ? sv : 0.0f;
    scores[p] = score;

    // ---------- fused stats + compaction epilogue ----------
    int lane = tid & 31, warp = tid >> 5;
    bool selp = (score > 0.7f);
    unsigned int bal = __ballot_sync(0xFFFFFFFFu, selp);
    int wcnt = __popc(bal);
    int myoff = __popc(bal & ((1u << lane) - 1u));

    float sum = score, sq = score * score;
    int mc = (m != 0);
    for (int o = 16; o; o >>= 1) {
        sum += __shfl_down_sync(0xFFFFFFFFu, sum, o);
        sq  += __shfl_down_sync(0xFFFFFFFFu, sq, o);
        mc  += __shfl_down_sync(0xFFFFFFFFu, mc, o);
    }
    if (lane == 0) { rsum[warp] = sum; rsq[warp] = sq; rcnt[warp] = wcnt; rmask[warp] = mc; }
    __syncthreads();
    if (tid == 0) {
        float ts = 0.f, tq = 0.f; int tc = 0, tm = 0;
#pragma unroll
        for (int w = 0; w < 8; w++) {
            roff[w] = tc;
            ts += rsum[w]; tq += rsq[w]; tc += rcnt[w]; tm += rmask[w];
        }
        int cid = blockIdx.x;            // chunk id == CTA id
        g_csum[cid] = ts; g_csq[cid] = tq; g_ccnt[cid] = tc; g_cmask[cid] = tm;
    }
    __syncthreads();
    if (selp) {
        int bloc = p >> 13;              // batch
        int chunk = (blockIdx.x & (CPB - 1));
        g_sel[bloc][chunk * 256 + roff[warp] + myoff] = p & (NN - 1);
    }
}

// ============================================================
// Kernel 2: per-batch finalize. grid=4, 1024 threads.
// Reduces chunk stats, gates, gathers compacted selected lists
// (chunk order => globally ascending), pair distances, conf.
// ============================================================
__global__ __launch_bounds__(1024) void conf_kernel(
    const float* __restrict__ points,
    float* __restrict__ scores_out, float* __restrict__ conf_out)
{
    __shared__ int sel[NN];             // 32 KB
    __shared__ int cpref[CPB], ccnt_s[CPB];
    __shared__ float s_sum, s_sq;
    __shared__ int s_cnt, s_nleaf;
    __shared__ float wsd[32], wsd2[32];

    int b = blockIdx.x;
    int tid = threadIdx.x;
    int lane = tid & 31, warp = tid >> 5;
    const float* P = points + (size_t)b * NN * 3;

    // warp 0: reduce + prefix the 32 chunk records
    if (warp == 0) {
        int cid = b * CPB + lane;
        float cs = g_csum[cid], cq = g_csq[cid];
        int cc = g_ccnt[cid], cm = g_cmask[cid];
        ccnt_s[lane] = cc;
        // inclusive scan of cc
        int incl = cc;
        for (int o = 1; o < 32; o <<= 1) {
            int t = __shfl_up_sync(0xFFFFFFFFu, incl, o);
            if (lane >= o) incl += t;
        }
        cpref[lane] = incl - cc;         // exclusive prefix
        float ts = cs, tq = cq; int tm = cm;
        for (int o = 16; o; o >>= 1) {
            ts += __shfl_down_sync(0xFFFFFFFFu, ts, o);
            tq += __shfl_down_sync(0xFFFFFFFFu, tq, o);
            tm += __shfl_down_sync(0xFFFFFFFFu, tm, o);
        }
        if (lane == 0) { s_sum = ts; s_sq = tq; s_nleaf = tm; }
        if (lane == 31) s_cnt = incl;
    }
    __syncthreads();

    int nleaf = s_nleaf;
    if (nleaf < 10) {
        // reference zeroes all scores for this batch; conf = 0
        float4 zz = make_float4(0.f, 0.f, 0.f, 0.f);
        float4* so4 = (float4*)(scores_out + b * NN) + tid * 2;
        so4[0] = zz; so4[1] = zz;
        if (tid == 0) conf_out[b] = 0.0f;
        return;
    }

    // gather chunk lists into contiguous ascending order (warp w -> chunk w)
    {
        int cc = ccnt_s[warp];
        int dst = cpref[warp];
        for (int j = lane; j < cc; j += 32)
            sel[dst + j] = g_sel[b][warp * 256 + j];
    }
    __syncthreads();

    int cnt = s_cnt;
    int pc = cnt - 1;
    float sd = 0.0f, sd2 = 0.0f;
    for (int q = tid; q < pc; q += 1024) {
        int i1 = sel[q], i2 = sel[q + 1];
        float dx = P[i2 * 3 + 0] - P[i1 * 3 + 0];
        float dy = P[i2 * 3 + 1] - P[i1 * 3 + 1];
        float dz = P[i2 * 3 + 2] - P[i1 * 3 + 2];
        float d = sqrtf(dx * dx + dy * dy + dz * dz);
        sd += d; sd2 += d * d;
    }
    for (int o = 16; o; o >>= 1) {
        sd  += __shfl_down_sync(0xFFFFFFFFu, sd, o);
        sd2 += __shfl_down_sync(0xFFFFFFFFu, sd2, o);
    }
    if (lane == 0) { wsd[warp] = sd; wsd2[warp] = sd2; }
    __syncthreads();

    if (tid == 0) {
        float tsd = 0.f, tsd2 = 0.f;
        for (int w = 0; w < 32; w++) { tsd += wsd[w]; tsd2 += wsd2[w]; }
        float tsum = s_sum, tsq = s_sq;
        float nl = (float)nleaf;
        float mean = tsum / fmaxf(nl, 1.0f);
        float clarity = (tsq - 2.0f * mean * tsum + mean * mean * nl)
                        / fmaxf(nl - 1.0f, 1.0f);
        float pcf = (float)(pc > 0 ? pc : 0);
        float meand = tsd / fmaxf(pcf, 1.0f);
        float dvar = (tsd2 - 2.0f * meand * tsd + meand * meand * pcf)
                     / fmaxf(pcf - 1.0f, 1.0f);
        float cont = fminf(fmaxf(1.0f / (dvar + 1e-8f), 0.0f), 1.0f);
        cont = (cnt > 5) ? cont : 0.0f;
        float conf = fminf(fmaxf(clarity * cont, 0.0f), 1.0f);
        conf = (nleaf == 0) ? 0.0f : conf;
        conf_out[b] = conf;
    }
}

// ============================================================
// launch
// ============================================================
extern "C" void kernel_launch(void* const* d_in, const int* in_sizes, int n_in,
                              void* d_out, int out_size) {
    const float* points   = (const float*)d_in[0];
    const float* features = (const float*)d_in[1];
    const int*   mask     = (const int*)d_in[2];
    const float* W1 = (const float*)d_in[3];
    const float* b1 = (const float*)d_in[4];
    const float* W2 = (const float*)d_in[5];
    const float* b2 = (const float*)d_in[6];
    const float* W3 = (const float*)d_in[7];
    const float* b3 = (const float*)d_in[8];

    float* out_scores = (float*)d_out;                       // [B*N]
    float* out_feats  = out_scores + BB * NN;                // [B*N*F]
    float* out_conf   = out_feats + (size_t)BB * NN * FF;    // [B]

    mlp_kernel<<<(BB * NN) / 256, 256>>>(points, features, mask,
                                         W1, b1, W2, b2, W3, b3,
                                         out_scores, out_feats);

    conf_kernel<<<BB, 1024>>>(points, out_scores, out_conf);
}

// round 7
// speedup vs baseline: 1.0013x; 1.0013x over previous
#include <cuda_runtime.h>
#include <cuda_fp16.h>
#include <math.h>

#define BB 4
#define NN 8192
#define FF 64
#define H1 64
#define H2 32
#define K2P 36            // padded half2 pairs per W1 row (67 inputs + bias + pad)
#define CPB 32            // CTAs (chunks) per batch = 8192/256

__device__ __forceinline__ __half2 u2h2(unsigned int u) {
    return *reinterpret_cast<__half2*>(&u);
}

// ---- scratch (static, no allocation) ----
__device__ float g_csum[BB * CPB];
__device__ float g_csq[BB * CPB];
__device__ int   g_ccnt[BB * CPB];     // selected (>0.7) per chunk
__device__ int   g_cmask[BB * CPB];    // mask count per chunk
__device__ int   g_sel[BB][NN];        // per-chunk compacted selected indices
__device__ int   g_done[BB];           // zero-initialized; reset after each use

// ============================================================
// Single kernel: per-point MLP 67 -> 64 -> 32 -> 1 (+mask) in fp16x2,
// fused per-chunk stats + compaction epilogue, and last-CTA-per-batch
// finalize (gate, gather, pair distances, confidence).
// ============================================================
__global__ __launch_bounds__(256) void mlp_kernel(
    const float* __restrict__ points, const float* __restrict__ features,
    const int* __restrict__ mask,
    const float* __restrict__ W1, const float* __restrict__ b1,
    const float* __restrict__ W2, const float* __restrict__ b2,
    const float* __restrict__ W3, const float* __restrict__ b3,
    float* __restrict__ scores, float* __restrict__ out_feats,
    float* __restrict__ conf_out)
{
    __shared__ __align__(16) __half2 sW1h[H1][K2P];   // 9216B
    __shared__ __align__(16) __half2 sW2h[H2][H1/2];  // 4096B
    __shared__ float sb2[H2];
    __shared__ float sW3[H2];
    __shared__ float sb3;
    __shared__ float rsum[8], rsq[8];
    __shared__ int rcnt[8], rmask[8], roff[8];
    // finalize-only shared state (used by the last CTA of each batch)
    __shared__ int sel[NN];            // 32 KB
    __shared__ int cpref[CPB], ccnt_s[CPB];
    __shared__ float f_sum, f_sq;
    __shared__ int f_cnt, f_nleaf, s_last;
    __shared__ float wsd[8], wsd2[8];

    int tid = threadIdx.x;
    int lane = tid & 31, warp = tid >> 5;

    // ---- pack W1 (+bias1) into half2 [64][36] ----
    for (int idx = tid; idx < H1 * K2P; idx += 256) {
        int j = idx / K2P, k2 = idx % K2P;
        float a = 0.f, bv = 0.f;
        if (k2 <= 33) {
            int k = 2 * k2;
            a  = (k     < 67) ? W1[j * 67 + k]     : 0.f;
            bv = (k + 1 < 67) ? W1[j * 67 + k + 1] : 0.f;
        } else if (k2 == 34) {
            a = b1[j];                 // bias slot, x2[34] = (1, 0)
        }
        sW1h[j][k2] = __floats2half2_rn(a, bv);
    }
    // ---- pack W2 into half2 [32][32] ----
    for (int idx = tid; idx < H2 * (H1 / 2); idx += 256) {
        int i = idx / (H1 / 2), j2 = idx % (H1 / 2);
        sW2h[i][j2] = __floats2half2_rn(W2[i * H1 + 2 * j2], W2[i * H1 + 2 * j2 + 1]);
    }
    if (tid < H2) { sb2[tid] = b2[tid]; sW3[tid] = W3[tid]; }
    if (tid == 0) sb3 = b3[0];
    __syncthreads();

    int p = blockIdx.x * 256 + tid;   // global point id over B*N (grid exact)

    // ---- load input, stream features passthrough, pack x to half2 ----
    __half2 x2[K2P];
    const float4* f4 = (const float4*)(features + (size_t)p * FF);
    float4* o4 = (float4*)(out_feats + (size_t)p * FF);
#pragma unroll
    for (int i = 0; i < FF / 4; i++) {
        float4 v = f4[i];
        o4[i] = v;
        x2[2 * i]     = __floats2half2_rn(v.x, v.y);
        x2[2 * i + 1] = __floats2half2_rn(v.z, v.w);
    }
    const float* pp = points + (size_t)p * 3;
    x2[32] = __floats2half2_rn(pp[0], pp[1]);
    x2[33] = __floats2half2_rn(pp[2], 0.f);
    x2[34] = __floats2half2_rn(1.f, 0.f);     // bias slot
    x2[35] = __floats2half2_rn(0.f, 0.f);

    // ---- layer-2 accumulators initialized with bias (lane 0) ----
    __half2 h2acc[H2];
#pragma unroll
    for (int i = 0; i < H2; i++) h2acc[i] = __floats2half2_rn(sb2[i], 0.f);

    // ---- layer 1 in groups of 8 outputs, streamed into layer 2 ----
    for (int jg = 0; jg < H1 / 8; jg++) {
        float h[8];
#pragma unroll
        for (int jj = 0; jj < 8; jj++) {
            const uint4* row = reinterpret_cast<const uint4*>(sW1h[jg * 8 + jj]);
            __half2 aa = __floats2half2_rn(0.f, 0.f);
            __half2 ab = __floats2half2_rn(0.f, 0.f);
#pragma unroll
            for (int q = 0; q < 9; q++) {
                uint4 w = row[q];
                aa = __hfma2(u2h2(w.x), x2[4 * q],     aa);
                ab = __hfma2(u2h2(w.y), x2[4 * q + 1], ab);
                aa = __hfma2(u2h2(w.z), x2[4 * q + 2], aa);
                ab = __hfma2(u2h2(w.w), x2[4 * q + 3], ab);
            }
            float2 f = __half22float2(__hadd2(aa, ab));
            h[jj] = fmaxf(f.x + f.y, 0.f);
        }
        __half2 hp[4];
#pragma unroll
        for (int t = 0; t < 4; t++) hp[t] = __floats2half2_rn(h[2 * t], h[2 * t + 1]);

#pragma unroll
        for (int i = 0; i < H2; i++) {
            uint4 w = reinterpret_cast<const uint4*>(sW2h[i])[jg];
            h2acc[i] = __hfma2(u2h2(w.x), hp[0], h2acc[i]);
            h2acc[i] = __hfma2(u2h2(w.y), hp[1], h2acc[i]);
            h2acc[i] = __hfma2(u2h2(w.z), hp[2], h2acc[i]);
            h2acc[i] = __hfma2(u2h2(w.w), hp[3], h2acc[i]);
        }
    }

    // ---- layer 3 (fp32): relu(h2) dot W3, 4 chains ----
    float z0 = 0.f, z1 = 0.f, z2 = 0.f, z3 = 0.f;
#pragma unroll
    for (int i = 0; i < H2; i += 4) {
        float2 f0 = __half22float2(h2acc[i]);
        float2 f1 = __half22float2(h2acc[i + 1]);
        float2 f2 = __half22float2(h2acc[i + 2]);
        float2 f3 = __half22float2(h2acc[i + 3]);
        z0 += sW3[i]     * fmaxf(f0.x + f0.y, 0.f);
        z1 += sW3[i + 1] * fmaxf(f1.x + f1.y, 0.f);
        z2 += sW3[i + 2] * fmaxf(f2.x + f2.y, 0.f);
        z3 += sW3[i + 3] * fmaxf(f3.x + f3.y, 0.f);
    }
    float z = sb3 + (z0 + z1) + (z2 + z3);
    float sv = 1.0f / (1.0f + expf(-z));

    int m = mask[p];
    float score = (m != 0) ? sv : 0.0f;
    scores[p] = score;

    // ---------- fused stats + compaction epilogue ----------
    bool selp = (score > 0.7f);
    unsigned int bal = __ballot_sync(0xFFFFFFFFu, selp);
    int wcnt = __popc(bal);
    int myoff = __popc(bal & ((1u << lane) - 1u));

    float sum = score, sq = score * score;
    int mc = (m != 0);
    for (int o = 16; o; o >>= 1) {
        sum += __shfl_down_sync(0xFFFFFFFFu, sum, o);
        sq  += __shfl_down_sync(0xFFFFFFFFu, sq, o);
        mc  += __shfl_down_sync(0xFFFFFFFFu, mc, o);
    }
    if (lane == 0) { rsum[warp] = sum; rsq[warp] = sq; rcnt[warp] = wcnt; rmask[warp] = mc; }
    __syncthreads();
    if (tid == 0) {
        float ts = 0.f, tq = 0.f; int tc = 0, tm = 0;
#pragma unroll
        for (int w = 0; w < 8; w++) {
            roff[w] = tc;
            ts += rsum[w]; tq += rsq[w]; tc += rcnt[w]; tm += rmask[w];
        }
        int cid = blockIdx.x;            // chunk id == CTA id
        g_csum[cid] = ts; g_csq[cid] = tq; g_ccnt[cid] = tc; g_cmask[cid] = tm;
    }
    __syncthreads();
    int fb = blockIdx.x / CPB;           // batch of this CTA
    if (selp) {
        int chunk = blockIdx.x & (CPB - 1);
        g_sel[fb][chunk * 256 + roff[warp] + myoff] = p & (NN - 1);
    }

    // ---------- last-CTA-per-batch finalize ----------
    __threadfence();                     // publish this CTA's global writes
    __syncthreads();
    if (tid == 0) {
        int done = atomicAdd(&g_done[fb], 1);
        s_last = (done == CPB - 1) ? 1 : 0;
    }
    __syncthreads();
    if (!s_last) return;
    __threadfence();                     // acquire side

    // warp 0: reduce + prefix the 32 chunk records of batch fb
    if (warp == 0) {
        int cid = fb * CPB + lane;
        float cs = g_csum[cid], cq = g_csq[cid];
        int cc = g_ccnt[cid], cm = g_cmask[cid];
        ccnt_s[lane] = cc;
        int incl = cc;
        for (int o = 1; o < 32; o <<= 1) {
            int t = __shfl_up_sync(0xFFFFFFFFu, incl, o);
            if (lane >= o) incl += t;
        }
        cpref[lane] = incl - cc;         // exclusive prefix
        float ts = cs, tq = cq; int tm = cm;
        for (int o = 16; o; o >>= 1) {
            ts += __shfl_down_sync(0xFFFFFFFFu, ts, o);
            tq += __shfl_down_sync(0xFFFFFFFFu, tq, o);
            tm += __shfl_down_sync(0xFFFFFFFFu, tm, o);
        }
        if (lane == 0) { f_sum = ts; f_sq = tq; f_nleaf = tm; }
        if (lane == 31) f_cnt = incl;
    }
    __syncthreads();

    int nleaf = f_nleaf;
    if (nleaf < 10) {
        // reference zeroes all scores for this batch; conf = 0
        float4 zz = make_float4(0.f, 0.f, 0.f, 0.f);
        float4* so4 = (float4*)(scores + fb * NN);
        for (int i = tid; i < NN / 4; i += 256) so4[i] = zz;
        if (tid == 0) { conf_out[fb] = 0.0f; g_done[fb] = 0; }
        return;
    }

    // gather chunk lists into contiguous ascending order
    for (int c2 = warp; c2 < CPB; c2 += 8) {
        int cc = ccnt_s[c2];
        int dst = cpref[c2];
        for (int j = lane; j < cc; j += 32)
            sel[dst + j] = g_sel[fb][c2 * 256 + j];
    }
    __syncthreads();

    const float* P = points + (size_t)fb * NN * 3;
    int cnt = f_cnt;
    int pc = cnt - 1;
    float sd = 0.0f, sd2 = 0.0f;
    for (int q = tid; q < pc; q += 256) {
        int i1 = sel[q], i2 = sel[q + 1];
        float dx = P[i2 * 3 + 0] - P[i1 * 3 + 0];
        float dy = P[i2 * 3 + 1] - P[i1 * 3 + 1];
        float dz = P[i2 * 3 + 2] - P[i1 * 3 + 2];
        float d = sqrtf(dx * dx + dy * dy + dz * dz);
        sd += d; sd2 += d * d;
    }
    for (int o = 16; o; o >>= 1) {
        sd  += __shfl_down_sync(0xFFFFFFFFu, sd, o);
        sd2 += __shfl_down_sync(0xFFFFFFFFu, sd2, o);
    }
    if (lane == 0) { wsd[warp] = sd; wsd2[warp] = sd2; }
    __syncthreads();

    if (tid == 0) {
        float tsd = 0.f, tsd2 = 0.f;
#pragma unroll
        for (int w = 0; w < 8; w++) { tsd += wsd[w]; tsd2 += wsd2[w]; }
        float tsum = f_sum, tsq = f_sq;
        float nl = (float)nleaf;
        float mean = tsum / fmaxf(nl, 1.0f);
        float clarity = (tsq - 2.0f * mean * tsum + mean * mean * nl)
                        / fmaxf(nl - 1.0f, 1.0f);
        float pcf = (float)(pc > 0 ? pc : 0);
        float meand = tsd / fmaxf(pcf, 1.0f);
        float dvar = (tsd2 - 2.0f * meand * tsd + meand * meand * pcf)
                     / fmaxf(pcf - 1.0f, 1.0f);
        float cont = fminf(fmaxf(1.0f / (dvar + 1e-8f), 0.0f), 1.0f);
        cont = (cnt > 5) ? cont : 0.0f;
        float conf = fminf(fmaxf(clarity * cont, 0.0f), 1.0f);
        conf = (nleaf == 0) ? 0.0f : conf;
        conf_out[fb] = conf;
        g_done[fb] = 0;                  // restore invariant for next replay
    }
}

// ============================================================
// launch — single kernel
// ============================================================
extern "C" void kernel_launch(void* const* d_in, const int* in_sizes, int n_in,
                              void* d_out, int out_size) {
    const float* points   = (const float*)d_in[0];
    const float* features = (const float*)d_in[1];
    const int*   mask     = (const int*)d_in[2];
    const float* W1 = (const float*)d_in[3];
    const float* b1 = (const float*)d_in[4];
    const float* W2 = (const float*)d_in[5];
    const float* b2 = (const float*)d_in[6];
    const float* W3 = (const float*)d_in[7];
    const float* b3 = (const float*)d_in[8];

    float* out_scores = (float*)d_out;                       // [B*N]
    float* out_feats  = out_scores + BB * NN;                // [B*N*F]
    float* out_conf   = out_feats + (size_t)BB * NN * FF;    // [B]

    mlp_kernel<<<(BB * NN) / 256, 256>>>(points, features, mask,
                                         W1, b1, W2, b2, W3, b3,
                                         out_scores, out_feats, out_conf);
}